// round 2
// baseline (speedup 1.0000x reference)
#include <cuda_runtime.h>
#include <math.h>
#include <float.h>

#define NROWS 200000
#define NBAGS 25000
#define DIM   690
#define NREL  53

// ---------------- scratch (device globals: allocation-free) ----------------
__device__ float g_rlog[NROWS];                     // per-row logits
__device__ float g_w[NROWS];                        // per-row softmax weights
__device__ float g_att[(size_t)NBAGS * DIM];        // bag representations (69 MB)
__device__ float g_relT[(size_t)DIM * NREL];        // relation_mat transposed [d][r]

// ---------------- K0: transpose relation_mat (tiny) ----------------
__global__ void k_transpose_rel(const float* __restrict__ rel) {
    int i = blockIdx.x * blockDim.x + threadIdx.x;
    if (i < DIM * NREL) {
        int d = i / NREL, r = i % NREL;
        g_relT[i] = rel[(size_t)r * DIM + d];
    }
}

// ---------------- K1: rel_logits[i] = repre[i] . rel[labels[i]] ----------------
// one warp per row, float2 loads (rows are 8B aligned: 690*4 = 2760 bytes)
__global__ void k_rowdot(const float* __restrict__ repre,
                         const float* __restrict__ rel,
                         const int* __restrict__ labels) {
    int row = blockIdx.x * blockDim.y + threadIdx.y;
    if (row >= NROWS) return;
    const float2* a = (const float2*)(repre + (size_t)row * DIM);
    const float2* b = (const float2*)(rel + (size_t)labels[row] * DIM);
    float s = 0.f;
    for (int j = threadIdx.x; j < DIM / 2; j += 32) {  // 345 float2
        float2 x = a[j], y = b[j];
        s = fmaf(x.x, y.x, s);
        s = fmaf(x.y, y.y, s);
    }
#pragma unroll
    for (int o = 16; o; o >>= 1) s += __shfl_xor_sync(0xffffffffu, s, o);
    if (threadIdx.x == 0) g_rlog[row] = s;
}

// ---------------- K2: per-bag softmax -> weights ----------------
// one warp per bag (bags avg 8 rows)
__global__ void k_softmax(const int* __restrict__ scope) {
    int bag = blockIdx.x * blockDim.y + threadIdx.y;
    if (bag >= NBAGS) return;
    int s = scope[2 * bag];
    int e = scope[2 * bag + 1];
    float m = -FLT_MAX;
    for (int i = s + threadIdx.x; i < e; i += 32) m = fmaxf(m, g_rlog[i]);
#pragma unroll
    for (int o = 16; o; o >>= 1) m = fmaxf(m, __shfl_xor_sync(0xffffffffu, m, o));
    float sum = 0.f;
    for (int i = s + threadIdx.x; i < e; i += 32) sum += expf(g_rlog[i] - m);
#pragma unroll
    for (int o = 16; o; o >>= 1) sum += __shfl_xor_sync(0xffffffffu, sum, o);
    float inv = 1.f / sum;
    for (int i = s + threadIdx.x; i < e; i += 32)
        g_w[i] = expf(g_rlog[i] - m) * inv;
}

// ---------------- K3: att[bag][d] = sum_i w_i * repre[i][d] ----------------
// one block per bag; threads stride over d -> coalesced repre reads
__global__ void k_att(const float* __restrict__ repre,
                      const int* __restrict__ scope) {
    int bag = blockIdx.x;
    int s = scope[2 * bag];
    int e = scope[2 * bag + 1];
    for (int d = threadIdx.x; d < DIM; d += blockDim.x) {
        float acc = 0.f;
        for (int i = s; i < e; i++)
            acc = fmaf(g_w[i], repre[(size_t)i * DIM + d], acc);
        g_att[(size_t)bag * DIM + d] = acc;
    }
}

// ---------------- K4: logits = att @ rel^T + bias ----------------
// register-tiled GEMM: block tile 64 bags x 64 r (53 real), K chunks of 32
#define TB 64
#define TR 64
#define TK 32
#define ATT_LD (TK + 2)   // pad to dodge staging bank conflicts

__global__ void k_gemm(const float* __restrict__ bias,
                       float* __restrict__ out) {
    __shared__ float att_s[TB][ATT_LD];   // [bag][k]
    __shared__ float rel_s[TK][TR];       // [k][r]  (row = 256B, float4 aligned)

    int bag0 = blockIdx.x * TB;
    int tx = threadIdx.x & 15;   // r group: r = tx*4 .. tx*4+3
    int ty = threadIdx.x >> 4;   // bag group: bag = ty*4 .. ty*4+3
    float acc[4][4] = {};

    for (int k0 = 0; k0 < DIM; k0 += TK) {
        // stage att tile: coalesced float2 global reads
        for (int t = threadIdx.x; t < TB * (TK / 2); t += 256) {
            int row = t / (TK / 2);
            int c2  = t % (TK / 2);
            int d   = k0 + c2 * 2;
            int bag = bag0 + row;
            float2 v = make_float2(0.f, 0.f);
            if (bag < NBAGS && d + 1 < DIM)
                v = *(const float2*)(g_att + (size_t)bag * DIM + d);
            else if (bag < NBAGS && d < DIM)
                v.x = g_att[(size_t)bag * DIM + d];
            att_s[row][c2 * 2 + 0] = v.x;
            att_s[row][c2 * 2 + 1] = v.y;
        }
        // stage rel tile from transposed copy
        for (int t = threadIdx.x; t < TK * TR; t += 256) {
            int k = t / TR, r = t % TR;
            int d = k0 + k;
            rel_s[k][r] = (d < DIM && r < NREL) ? g_relT[(size_t)d * NREL + r] : 0.f;
        }
        __syncthreads();

#pragma unroll
        for (int k = 0; k < TK; k++) {
            float4 b4 = *(const float4*)&rel_s[k][tx * 4];
            float a0 = att_s[ty * 4 + 0][k];
            float a1 = att_s[ty * 4 + 1][k];
            float a2 = att_s[ty * 4 + 2][k];
            float a3 = att_s[ty * 4 + 3][k];
            acc[0][0] = fmaf(a0, b4.x, acc[0][0]);
            acc[0][1] = fmaf(a0, b4.y, acc[0][1]);
            acc[0][2] = fmaf(a0, b4.z, acc[0][2]);
            acc[0][3] = fmaf(a0, b4.w, acc[0][3]);
            acc[1][0] = fmaf(a1, b4.x, acc[1][0]);
            acc[1][1] = fmaf(a1, b4.y, acc[1][1]);
            acc[1][2] = fmaf(a1, b4.z, acc[1][2]);
            acc[1][3] = fmaf(a1, b4.w, acc[1][3]);
            acc[2][0] = fmaf(a2, b4.x, acc[2][0]);
            acc[2][1] = fmaf(a2, b4.y, acc[2][1]);
            acc[2][2] = fmaf(a2, b4.z, acc[2][2]);
            acc[2][3] = fmaf(a2, b4.w, acc[2][3]);
            acc[3][0] = fmaf(a3, b4.x, acc[3][0]);
            acc[3][1] = fmaf(a3, b4.y, acc[3][1]);
            acc[3][2] = fmaf(a3, b4.z, acc[3][2]);
            acc[3][3] = fmaf(a3, b4.w, acc[3][3]);
        }
        __syncthreads();
    }

#pragma unroll
    for (int i = 0; i < 4; i++) {
        int bag = bag0 + ty * 4 + i;
        if (bag >= NBAGS) continue;
#pragma unroll
        for (int j = 0; j < 4; j++) {
            int r = tx * 4 + j;
            if (r < NREL)
                out[(size_t)bag * NREL + r] = acc[i][j] + bias[r];
        }
    }
}

// ---------------- launch ----------------
extern "C" void kernel_launch(void* const* d_in, const int* in_sizes, int n_in,
                              void* d_out, int out_size) {
    const float* repre  = (const float*)d_in[0];   // [N, D]
    const float* rel    = (const float*)d_in[1];   // [R, D]
    const float* bias   = (const float*)d_in[2];   // [R]
    const int* scope    = (const int*)d_in[3];     // [NBAGS, 2] (int32: JAX x64 off)
    const int* labels   = (const int*)d_in[4];     // [N]        (int32)
    float* out = (float*)d_out;                    // [NBAGS, R]

    (void)in_sizes; (void)n_in; (void)out_size;

    // K0: transpose relation_mat
    {
        int total = DIM * NREL;
        k_transpose_rel<<<(total + 255) / 256, 256>>>(rel);
    }
    // K1: per-row logits (1 warp/row, 8 warps/block)
    {
        dim3 blk(32, 8);
        int grid = (NROWS + 7) / 8;
        k_rowdot<<<grid, blk>>>(repre, rel, labels);
    }
    // K2: per-bag softmax (1 warp/bag)
    {
        dim3 blk(32, 8);
        int grid = (NBAGS + 7) / 8;
        k_softmax<<<grid, blk>>>(scope);
    }
    // K3: bag attention-weighted sums (1 block/bag)
    {
        k_att<<<NBAGS, 256>>>(repre, scope);
    }
    // K4: final GEMM + bias
    {
        int grid = (NBAGS + TB - 1) / TB;   // 391 blocks
        k_gemm<<<grid, 256>>>(bias, out);
    }
}

// round 3
// speedup vs baseline: 1.1636x; 1.1636x over previous
#include <cuda_runtime.h>
#include <math.h>
#include <float.h>

#define NROWS 200000
#define NBAGS 25000
#define DIM   690
#define NREL  53
#define SMAX  4096   // shared logit slots per bag (avg bag = 8; max gap ~ 100)

// ---------------- scratch (device globals: allocation-free) ----------------
__device__ float g_w[NROWS];                        // fallback weight scratch
__device__ float g_att[(size_t)NBAGS * DIM];        // bag representations (69 MB)
__device__ float g_relT[(size_t)DIM * NREL];        // relation_mat transposed [d][r]

// ---------------- K0: transpose relation_mat (tiny) ----------------
__global__ void k_transpose_rel(const float* __restrict__ rel) {
    int i = blockIdx.x * blockDim.x + threadIdx.x;
    if (i < DIM * NREL) {
        int d = i / NREL, r = i % NREL;
        g_relT[i] = rel[(size_t)r * DIM + d];
    }
}

// ---------------- K1: fused per-bag (row dots -> softmax -> weighted sum) ----
// one block (8 warps) per bag
__global__ __launch_bounds__(256) void k_bag_fused(
    const float* __restrict__ repre,
    const float* __restrict__ rel,
    const int* __restrict__ labels,
    const int* __restrict__ scope)
{
    __shared__ float lbuf_s[SMAX];
    __shared__ float red[10];

    int bag = blockIdx.x;
    int s = scope[2 * bag];
    int e = scope[2 * bag + 1];
    int c = e - s;

    float* lbuf = (c <= SMAX) ? lbuf_s : (g_w + s);   // generic-space ptr

    int wid  = threadIdx.x >> 5;
    int lane = threadIdx.x & 31;

    // ---- Phase A: rel_logits for each row in bag (warp per row) ----
    for (int i = s + wid; i < e; i += 8) {
        const float2* a = (const float2*)(repre + (size_t)i * DIM);
        const float2* b = (const float2*)(rel + (size_t)labels[i] * DIM);
        float sd = 0.f;
        for (int j = lane; j < DIM / 2; j += 32) {    // 345 float2
            float2 x = a[j], y = b[j];
            sd = fmaf(x.x, y.x, sd);
            sd = fmaf(x.y, y.y, sd);
        }
#pragma unroll
        for (int o = 16; o; o >>= 1) sd += __shfl_xor_sync(0xffffffffu, sd, o);
        if (lane == 0) lbuf[i - s] = sd;
    }
    __syncthreads();

    // ---- Phase B: block softmax over c logits ----
    float m = -FLT_MAX;
    for (int t = threadIdx.x; t < c; t += 256) m = fmaxf(m, lbuf[t]);
#pragma unroll
    for (int o = 16; o; o >>= 1) m = fmaxf(m, __shfl_xor_sync(0xffffffffu, m, o));
    if (lane == 0) red[wid] = m;
    __syncthreads();
    if (threadIdx.x == 0) {
        float v = red[0];
#pragma unroll
        for (int k = 1; k < 8; k++) v = fmaxf(v, red[k]);
        red[8] = v;
    }
    __syncthreads();
    m = red[8];

    float sum = 0.f;
    for (int t = threadIdx.x; t < c; t += 256) sum += __expf(lbuf[t] - m);
#pragma unroll
    for (int o = 16; o; o >>= 1) sum += __shfl_xor_sync(0xffffffffu, sum, o);
    __syncthreads();                 // red[0..7] reuse
    if (lane == 0) red[wid] = sum;
    __syncthreads();
    if (threadIdx.x == 0) {
        float v = red[0];
#pragma unroll
        for (int k = 1; k < 8; k++) v += red[k];
        red[9] = 1.f / v;
    }
    __syncthreads();
    float inv = red[9];

    // weights in-place
    for (int t = threadIdx.x; t < c; t += 256)
        lbuf[t] = __expf(lbuf[t] - m) * inv;
    __syncthreads();

    // ---- Phase C: att[bag][d] = sum_i w_i * repre[s+i][d] (rows L2-hot) ----
    for (int d = threadIdx.x; d < DIM; d += 256) {
        float acc = 0.f;
        const float* rp = repre + (size_t)s * DIM + d;
        for (int i = 0; i < c; i++)
            acc = fmaf(lbuf[i], rp[(size_t)i * DIM], acc);
        g_att[(size_t)bag * DIM + d] = acc;
    }
}

// ---------------- K4: logits = att @ rel^T + bias ----------------
#define TB 64
#define TR 64
#define TK 32
#define ATT_LD (TK + 2)

__global__ void k_gemm(const float* __restrict__ bias,
                       float* __restrict__ out) {
    __shared__ float att_s[TB][ATT_LD];   // [bag][k]
    __shared__ float rel_s[TK][TR];       // [k][r]

    int bag0 = blockIdx.x * TB;
    int tx = threadIdx.x & 15;
    int ty = threadIdx.x >> 4;
    float acc[4][4] = {};

    for (int k0 = 0; k0 < DIM; k0 += TK) {
        for (int t = threadIdx.x; t < TB * (TK / 2); t += 256) {
            int row = t / (TK / 2);
            int c2  = t % (TK / 2);
            int d   = k0 + c2 * 2;
            int bag = bag0 + row;
            float2 v = make_float2(0.f, 0.f);
            if (bag < NBAGS && d + 1 < DIM)
                v = *(const float2*)(g_att + (size_t)bag * DIM + d);
            else if (bag < NBAGS && d < DIM)
                v.x = g_att[(size_t)bag * DIM + d];
            att_s[row][c2 * 2 + 0] = v.x;
            att_s[row][c2 * 2 + 1] = v.y;
        }
        for (int t = threadIdx.x; t < TK * TR; t += 256) {
            int k = t / TR, r = t % TR;
            int d = k0 + k;
            rel_s[k][r] = (d < DIM && r < NREL) ? g_relT[(size_t)d * NREL + r] : 0.f;
        }
        __syncthreads();

#pragma unroll
        for (int k = 0; k < TK; k++) {
            float4 b4 = *(const float4*)&rel_s[k][tx * 4];
            float a0 = att_s[ty * 4 + 0][k];
            float a1 = att_s[ty * 4 + 1][k];
            float a2 = att_s[ty * 4 + 2][k];
            float a3 = att_s[ty * 4 + 3][k];
            acc[0][0] = fmaf(a0, b4.x, acc[0][0]);
            acc[0][1] = fmaf(a0, b4.y, acc[0][1]);
            acc[0][2] = fmaf(a0, b4.z, acc[0][2]);
            acc[0][3] = fmaf(a0, b4.w, acc[0][3]);
            acc[1][0] = fmaf(a1, b4.x, acc[1][0]);
            acc[1][1] = fmaf(a1, b4.y, acc[1][1]);
            acc[1][2] = fmaf(a1, b4.z, acc[1][2]);
            acc[1][3] = fmaf(a1, b4.w, acc[1][3]);
            acc[2][0] = fmaf(a2, b4.x, acc[2][0]);
            acc[2][1] = fmaf(a2, b4.y, acc[2][1]);
            acc[2][2] = fmaf(a2, b4.z, acc[2][2]);
            acc[2][3] = fmaf(a2, b4.w, acc[2][3]);
            acc[3][0] = fmaf(a3, b4.x, acc[3][0]);
            acc[3][1] = fmaf(a3, b4.y, acc[3][1]);
            acc[3][2] = fmaf(a3, b4.z, acc[3][2]);
            acc[3][3] = fmaf(a3, b4.w, acc[3][3]);
        }
        __syncthreads();
    }

#pragma unroll
    for (int i = 0; i < 4; i++) {
        int bag = bag0 + ty * 4 + i;
        if (bag >= NBAGS) continue;
#pragma unroll
        for (int j = 0; j < 4; j++) {
            int r = tx * 4 + j;
            if (r < NREL)
                out[(size_t)bag * NREL + r] = acc[i][j] + bias[r];
        }
    }
}

// ---------------- launch ----------------
extern "C" void kernel_launch(void* const* d_in, const int* in_sizes, int n_in,
                              void* d_out, int out_size) {
    const float* repre  = (const float*)d_in[0];   // [N, D]
    const float* rel    = (const float*)d_in[1];   // [R, D]
    const float* bias   = (const float*)d_in[2];   // [R]
    const int* scope    = (const int*)d_in[3];     // [NBAGS, 2] int32
    const int* labels   = (const int*)d_in[4];     // [N]        int32
    float* out = (float*)d_out;                    // [NBAGS, R]

    (void)in_sizes; (void)n_in; (void)out_size;

    k_transpose_rel<<<(DIM * NREL + 255) / 256, 256>>>(rel);
    k_bag_fused<<<NBAGS, 256>>>(repre, rel, labels, scope);
    k_gemm<<<(NBAGS + TB - 1) / TB, 256>>>(bias, out);
}

// round 4
// speedup vs baseline: 1.3067x; 1.1230x over previous
#include <cuda_runtime.h>
#include <cuda_bf16.h>
#include <math.h>
#include <float.h>

#define NROWS 200000
#define NBAGS 25000
#define DIM   690
#define NREL  53
#define KPAD  704      // DIM padded to multiple of 32
#define NPAD  64       // NREL padded
#define BM    128      // rows per block tile
#define KC    32       // k chunk
#define APITCH 40      // smem pitch (bf16 elems): 80B row stride = 5x16B -> LDSM conflict-free
#define BPITCH 40
#define WCAP  128      // shared weight slots per bag

// ---------------- scratch (device globals: allocation-free) ----------------
__device__ __align__(16) float g_P[(size_t)NROWS * NPAD];       // 51.2 MB
__device__ __align__(16) __nv_bfloat16 g_Bhi[NPAD * KPAD];
__device__ __align__(16) __nv_bfloat16 g_Blo[NPAD * KPAD];
__device__ float g_wglob[NROWS];                                // fallback for huge bags

// ---------------- K0: build bf16 hi/lo B = rel (padded, [n][k]) ------------
__global__ void k_prep(const float* __restrict__ rel) {
    int idx = blockIdx.x * blockDim.x + threadIdx.x;
    if (idx >= NPAD * KPAD) return;
    int n = idx / KPAD, k = idx % KPAD;
    float v = (n < NREL && k < DIM) ? rel[n * DIM + k] : 0.f;
    __nv_bfloat16 hi = __float2bfloat16(v);
    g_Bhi[idx] = hi;
    g_Blo[idx] = __float2bfloat16(v - __bfloat162float(hi));
}

// ---------------- K1: P = repre @ rel^T via bf16 hi/lo mma.sync ------------
__device__ __forceinline__ void mma_bf16(float* c, const unsigned* a, const unsigned* b) {
    asm volatile(
        "mma.sync.aligned.m16n8k16.row.col.f32.bf16.bf16.f32 "
        "{%0,%1,%2,%3}, {%4,%5,%6,%7}, {%8,%9}, {%0,%1,%2,%3};"
        : "+f"(c[0]), "+f"(c[1]), "+f"(c[2]), "+f"(c[3])
        : "r"(a[0]), "r"(a[1]), "r"(a[2]), "r"(a[3]), "r"(b[0]), "r"(b[1]));
}
__device__ __forceinline__ void ldsm4(unsigned* r, unsigned addr) {
    asm volatile("ldmatrix.sync.aligned.m8n8.x4.shared.b16 {%0,%1,%2,%3}, [%4];"
                 : "=r"(r[0]), "=r"(r[1]), "=r"(r[2]), "=r"(r[3]) : "r"(addr));
}
__device__ __forceinline__ void ldsm2(unsigned* r, unsigned addr) {
    asm volatile("ldmatrix.sync.aligned.m8n8.x2.shared.b16 {%0,%1}, [%2];"
                 : "=r"(r[0]), "=r"(r[1]) : "r"(addr));
}

__global__ __launch_bounds__(256) void k_pgemm(const float* __restrict__ repre) {
    __shared__ __align__(16) __nv_bfloat16 sAhi[BM * APITCH];
    __shared__ __align__(16) __nv_bfloat16 sAlo[BM * APITCH];
    __shared__ __align__(16) __nv_bfloat16 sBhi[NPAD * BPITCH];
    __shared__ __align__(16) __nv_bfloat16 sBlo[NPAD * BPITCH];

    int row0 = blockIdx.x * BM;
    int tid = threadIdx.x;
    int wid = tid >> 5, lane = tid & 31;
    int grp = lane >> 2, thr = lane & 3;
    int wrow = wid * 16;                     // warp tile: rows [wrow, wrow+16) x 64 cols

    float acc[8][4];
#pragma unroll
    for (int j = 0; j < 8; j++)
#pragma unroll
        for (int q = 0; q < 4; q++) acc[j][q] = 0.f;

    // precompute ldmatrix lane addresses (offsets vary per k-step)
    unsigned aAhi = (unsigned)__cvta_generic_to_shared(sAhi);
    unsigned aAlo = (unsigned)__cvta_generic_to_shared(sAlo);
    unsigned aBhi = (unsigned)__cvta_generic_to_shared(sBhi);
    unsigned aBlo = (unsigned)__cvta_generic_to_shared(sBlo);
    int arow = wrow + (lane & 15);
    int acolsel = (lane >> 4) << 3;          // 0 or 8
    int brow = lane & 7;
    int bcolsel = lane & 8;                  // 0 or 8

    for (int k0 = 0; k0 < KPAD; k0 += KC) {
        // ---- stage A: 128 rows x 32 floats, convert to bf16 hi/lo ----
        {
            int r = tid >> 1;                        // 0..127
            int gr = row0 + r;
            int fbase = (tid & 1) * 16;              // floats [fbase, fbase+16)
            const float* src = repre + (size_t)gr * DIM + k0;
            __nv_bfloat16* dhi = sAhi + r * APITCH + fbase;
            __nv_bfloat16* dlo = sAlo + r * APITCH + fbase;
#pragma unroll
            for (int i = 0; i < 8; i++) {
                int k = i * 2;
                float2 v = make_float2(0.f, 0.f);
                if (gr < NROWS) {
                    int kg = k0 + fbase + k;
                    if (kg + 1 < DIM) v = *(const float2*)(src + fbase + k);
                    else if (kg < DIM) v.x = src[fbase + k];
                }
                __nv_bfloat16 hx = __float2bfloat16(v.x);
                __nv_bfloat16 hy = __float2bfloat16(v.y);
                *(__nv_bfloat162*)(dhi + k) =
                    __nv_bfloat162(hx, hy);
                *(__nv_bfloat162*)(dlo + k) =
                    __nv_bfloat162(__float2bfloat16(v.x - __bfloat162float(hx)),
                                   __float2bfloat16(v.y - __bfloat162float(hy)));
            }
        }
        // ---- stage B: 64 n x 32 k bf16 hi/lo (16B vector copies) ----
        {
            int n = tid >> 2;                        // 0..63
            int kk = (tid & 3) * 8;                  // 0,8,16,24
            *(uint4*)(sBhi + n * BPITCH + kk) = *(const uint4*)(g_Bhi + n * KPAD + k0 + kk);
            *(uint4*)(sBlo + n * BPITCH + kk) = *(const uint4*)(g_Blo + n * KPAD + k0 + kk);
        }
        __syncthreads();

        // ---- compute: 2 k-steps of 16 ----
#pragma unroll
        for (int ks = 0; ks < KC; ks += 16) {
            unsigned ahi[4], alo[4];
            unsigned aoff = (unsigned)((arow * APITCH + ks + acolsel) * 2);
            ldsm4(ahi, aAhi + aoff);
            ldsm4(alo, aAlo + aoff);
#pragma unroll
            for (int j = 0; j < 8; j++) {
                unsigned bhi[2], blo[2];
                unsigned boff = (unsigned)(((j * 8 + brow) * BPITCH + ks + bcolsel) * 2);
                ldsm2(bhi, aBhi + boff);
                ldsm2(blo, aBlo + boff);
                mma_bf16(acc[j], ahi, bhi);
                mma_bf16(acc[j], ahi, blo);
                mma_bf16(acc[j], alo, bhi);
            }
        }
        __syncthreads();
    }

    // ---- epilogue: write P ----
    int r1 = row0 + wrow + grp;
    int r2 = r1 + 8;
#pragma unroll
    for (int j = 0; j < 8; j++) {
        int col = j * 8 + thr * 2;
        if (r1 < NROWS)
            *(float2*)&g_P[(size_t)r1 * NPAD + col] = make_float2(acc[j][0], acc[j][1]);
        if (r2 < NROWS)
            *(float2*)&g_P[(size_t)r2 * NPAD + col] = make_float2(acc[j][2], acc[j][3]);
    }
}

// ---------------- K2: per-bag softmax + combine over P ---------------------
__global__ __launch_bounds__(256) void k_bags(const int* __restrict__ scope,
                                              const int* __restrict__ labels,
                                              const float* __restrict__ bias,
                                              float* __restrict__ out) {
    __shared__ float wbuf[8][WCAP];
    int wid = threadIdx.x >> 5, lane = threadIdx.x & 31;
    int bag = blockIdx.x * 8 + wid;
    if (bag >= NBAGS) return;
    int s = scope[2 * bag];
    int e = scope[2 * bag + 1];
    int c = e - s;
    float* w = (c <= WCAP) ? wbuf[wid] : (g_wglob + s);

    // logits (gather) + max
    float m = -FLT_MAX;
    for (int i = lane; i < c; i += 32) {
        int gi = s + i;
        float lg = g_P[(size_t)gi * NPAD + labels[gi]];
        w[i] = lg;
        m = fmaxf(m, lg);
    }
#pragma unroll
    for (int o = 16; o; o >>= 1) m = fmaxf(m, __shfl_xor_sync(0xffffffffu, m, o));

    // exp + sum
    float sum = 0.f;
    for (int i = lane; i < c; i += 32) {
        float ev = __expf(w[i] - m);
        w[i] = ev;
        sum += ev;
    }
#pragma unroll
    for (int o = 16; o; o >>= 1) sum += __shfl_xor_sync(0xffffffffu, sum, o);
    float inv = 1.f / sum;
    __syncwarp();

    // combine: lane covers r = lane and r = lane+32
    float o0 = 0.f, o1 = 0.f;
    int r1 = lane + 32;
    for (int i = 0; i < c; i++) {
        float wi = w[i] * inv;
        const float* p = g_P + (size_t)(s + i) * NPAD;
        o0 = fmaf(wi, p[lane], o0);
        if (r1 < NREL) o1 = fmaf(wi, p[r1], o1);
    }
    if (lane < NREL) out[(size_t)bag * NREL + lane] = o0 + bias[lane];
    if (r1 < NREL)   out[(size_t)bag * NREL + r1]   = o1 + bias[r1];
}

// ---------------- launch ----------------
extern "C" void kernel_launch(void* const* d_in, const int* in_sizes, int n_in,
                              void* d_out, int out_size) {
    const float* repre  = (const float*)d_in[0];   // [N, D]
    const float* rel    = (const float*)d_in[1];   // [R, D]
    const float* bias   = (const float*)d_in[2];   // [R]
    const int* scope    = (const int*)d_in[3];     // [NBAGS, 2] int32
    const int* labels   = (const int*)d_in[4];     // [N]        int32
    float* out = (float*)d_out;                    // [NBAGS, R]

    (void)in_sizes; (void)n_in; (void)out_size;

    k_prep<<<(NPAD * KPAD + 255) / 256, 256>>>(rel);
    k_pgemm<<<(NROWS + BM - 1) / BM, 256>>>(repre);
    k_bags<<<(NBAGS + 7) / 8, 256>>>(scope, labels, bias, out);
}